// round 9
// baseline (speedup 1.0000x reference)
#include <cuda_runtime.h>
#include <cuda_fp16.h>
#include <cstdint>

// Problem constants (GCNN3L: N=100000 nodes, F=64 features, 8 outputs)
#define NN 100000
#define EE 1600000
#define F  64
#define F2 32          // F in half2 units
#define OUTF 8

#define SCAN_B 256

// Scratch (static device globals -- no allocation allowed)
__device__ __align__(256) __half2 g_tmpA[(size_t)NN * F2];  // scaled messages, fp16, buf A
__device__ __align__(256) __half2 g_tmpB[(size_t)NN * F2];  // scaled messages, fp16, buf B
__device__ __align__(256) float g_dis[NN];                  // rsqrt(deg)
__device__ __align__(256) int   g_cnt[NN];                  // in-degree (excl. self loop)
__device__ __align__(256) int   g_rowstart[NN];             // scan -> start; after place -> end (= inclusive scan)
__device__ __align__(256) int   g_bsum[512];
__device__ __align__(256) int   g_boff[512];
__device__ __align__(256) int   g_esrc[EE];                 // per-edge src, dst-sorted

// ---------------------------------------------------------------------------
// CSR build
// ---------------------------------------------------------------------------
__global__ void k_count(const int* __restrict__ ei, int E) {
    int e4 = blockIdx.x * blockDim.x + threadIdx.x;
    if (e4 * 4 + 3 < E) {
        int4 d = *reinterpret_cast<const int4*>(ei + E + e4 * 4);
        atomicAdd(&g_cnt[d.x], 1);
        atomicAdd(&g_cnt[d.y], 1);
        atomicAdd(&g_cnt[d.z], 1);
        atomicAdd(&g_cnt[d.w], 1);
    } else {
        for (int e = e4 * 4; e < E; e++) atomicAdd(&g_cnt[ei[E + e]], 1);
    }
}

__global__ void k_scan1(int n) {   // block-local exclusive scan + dis
    __shared__ int s[SCAN_B];
    int i = blockIdx.x * SCAN_B + threadIdx.x;
    int v = (i < n) ? g_cnt[i] : 0;
    s[threadIdx.x] = v;
    __syncthreads();
    for (int off = 1; off < SCAN_B; off <<= 1) {
        int t = (threadIdx.x >= off) ? s[threadIdx.x - off] : 0;
        __syncthreads();
        s[threadIdx.x] += t;
        __syncthreads();
    }
    if (i < n) {
        g_rowstart[i] = s[threadIdx.x] - v;   // exclusive within block
        g_dis[i] = rsqrtf((float)(v + 1));    // +1 self loop
    }
    if (threadIdx.x == SCAN_B - 1) g_bsum[blockIdx.x] = s[SCAN_B - 1];
}

__global__ void k_scan2(int nb) {  // single block, 512 threads
    __shared__ int s[512];
    int v = (threadIdx.x < nb) ? g_bsum[threadIdx.x] : 0;
    s[threadIdx.x] = v;
    __syncthreads();
    for (int off = 1; off < 512; off <<= 1) {
        int t = (threadIdx.x >= off) ? s[threadIdx.x - off] : 0;
        __syncthreads();
        s[threadIdx.x] += t;
        __syncthreads();
    }
    if (threadIdx.x < nb) g_boff[threadIdx.x] = s[threadIdx.x] - v;  // exclusive
}

__global__ void k_scan3(int n) {
    int i = blockIdx.x * SCAN_B + threadIdx.x;
    if (i < n) g_rowstart[i] += g_boff[blockIdx.x];
}

// Place edges; atomicAdd on rowstart acts as cursor. After this kernel,
// rowstart[i] == row END == inclusive scan, so start(i) = rowstart[i-1].
__global__ void k_place(const int* __restrict__ ei, int E) {
    int e2 = blockIdx.x * blockDim.x + threadIdx.x;
    if (e2 * 2 + 1 < E) {
        int2 s = *reinterpret_cast<const int2*>(ei + e2 * 2);
        int2 d = *reinterpret_cast<const int2*>(ei + E + e2 * 2);
        g_esrc[atomicAdd(&g_rowstart[d.x], 1)] = s.x;
        g_esrc[atomicAdd(&g_rowstart[d.y], 1)] = s.y;
    } else {
        for (int e = e2 * 2; e < E; e++) {
            g_esrc[atomicAdd(&g_rowstart[ei[E + e]], 1)] = ei[e];
        }
    }
}

// ---------------------------------------------------------------------------
// Layer-1 GEMM: tmpA = fp16((x @ W1) * dis)
// ---------------------------------------------------------------------------
__global__ void __launch_bounds__(256) k_gemm1(
        const float* __restrict__ x,
        const float* __restrict__ W,
        int n) {
    __shared__ float Ws[F * F];
    __shared__ float hs[F][F + 1];

    int tid = threadIdx.x;
    int tx  = tid & 15;
    int ty  = tid >> 4;
    int row0 = blockIdx.x * F;

    for (int i = tid; i < F * F; i += 256) Ws[i] = W[i];
    for (int i = tid; i < F * F; i += 256) {
        int r = i >> 6, f = i & 63;
        int row = row0 + r;
        hs[r][f] = (row < n) ? x[(size_t)row * F + f] : 0.0f;
    }
    __syncthreads();

    int c0 = tx * 4, r0 = ty * 4;
    float acc[4][4];
#pragma unroll
    for (int i = 0; i < 4; i++)
#pragma unroll
        for (int j = 0; j < 4; j++) acc[i][j] = 0.0f;

#pragma unroll 8
    for (int k = 0; k < F; k++) {
        float4 wv = *reinterpret_cast<const float4*>(&Ws[k * F + c0]);
        float h0 = hs[r0 + 0][k], h1 = hs[r0 + 1][k];
        float h2 = hs[r0 + 2][k], h3 = hs[r0 + 3][k];
        acc[0][0] = fmaf(h0, wv.x, acc[0][0]); acc[0][1] = fmaf(h0, wv.y, acc[0][1]);
        acc[0][2] = fmaf(h0, wv.z, acc[0][2]); acc[0][3] = fmaf(h0, wv.w, acc[0][3]);
        acc[1][0] = fmaf(h1, wv.x, acc[1][0]); acc[1][1] = fmaf(h1, wv.y, acc[1][1]);
        acc[1][2] = fmaf(h1, wv.z, acc[1][2]); acc[1][3] = fmaf(h1, wv.w, acc[1][3]);
        acc[2][0] = fmaf(h2, wv.x, acc[2][0]); acc[2][1] = fmaf(h2, wv.y, acc[2][1]);
        acc[2][2] = fmaf(h2, wv.z, acc[2][2]); acc[2][3] = fmaf(h2, wv.w, acc[2][3]);
        acc[3][0] = fmaf(h3, wv.x, acc[3][0]); acc[3][1] = fmaf(h3, wv.y, acc[3][1]);
        acc[3][2] = fmaf(h3, wv.z, acc[3][2]); acc[3][3] = fmaf(h3, wv.w, acc[3][3]);
    }

#pragma unroll
    for (int i = 0; i < 4; i++) {
        int row = row0 + r0 + i;
        if (row < n) {
            float d = g_dis[row];
            __half2 h0 = __floats2half2_rn(acc[i][0] * d, acc[i][1] * d);
            __half2 h1 = __floats2half2_rn(acc[i][2] * d, acc[i][3] * d);
            uint2 pk;
            pk.x = *reinterpret_cast<unsigned int*>(&h0);
            pk.y = *reinterpret_cast<unsigned int*>(&h1);
            *reinterpret_cast<uint2*>(g_tmpA + (size_t)row * F2 + tx * 2) = pk;
        }
    }
}

// ---------------------------------------------------------------------------
// Fused layer: agg (fp16 gather, fp32 accumulate) + next GEMM (fp32)
//   h[r] = relu(b + dis[r] * (tin[r] + sum_src tin[src]))
//   tout[r] = fp16((h @ W) * dis[r])
// ---------------------------------------------------------------------------
__device__ __forceinline__ void acc_half4(float4& a, uint2 raw) {
    __half2 h0 = *reinterpret_cast<__half2*>(&raw.x);
    __half2 h1 = *reinterpret_cast<__half2*>(&raw.y);
    float2 f0 = __half22float2(h0);
    float2 f1 = __half22float2(h1);
    a.x += f0.x; a.y += f0.y; a.z += f1.x; a.w += f1.y;
}

__global__ void __launch_bounds__(256) k_fused(
        const __half2* __restrict__ tin,
        __half2* __restrict__ tout,
        const float* __restrict__ b,   // bias of the AGG layer
        const float* __restrict__ W,   // weights of the NEXT gemm
        int n) {
    __shared__ float Ws[F * F];
    __shared__ float hs[F][F + 1];

    int tid = threadIdx.x;
    int tx  = tid & 15;                 // half2-pair slice / col group
    int grp = tid >> 4;                 // node group 0..15
    int row0 = blockIdx.x * F;
    int c0 = tx * 4;                    // float column base
    int h0off = tx * 2;                 // half2 column base

    for (int i = tid; i < F * F; i += 256) Ws[i] = W[i];

    float4 bv = *reinterpret_cast<const float4*>(b + c0);

#pragma unroll
    for (int batch = 0; batch < 4; batch++) {
        int r = batch * 16 + grp;
        int node = row0 + r;
        if (node < n) {
            int end   = g_rowstart[node];                       // inclusive scan = end
            int start = (node > 0) ? g_rowstart[node - 1] : 0;  // prev end = start

            float4 a0 = make_float4(0.f, 0.f, 0.f, 0.f);
            float4 a1 = make_float4(0.f, 0.f, 0.f, 0.f);
            float4 a2 = make_float4(0.f, 0.f, 0.f, 0.f);
            float4 a3 = make_float4(0.f, 0.f, 0.f, 0.f);

            // self term
            acc_half4(a0, *reinterpret_cast<const uint2*>(tin + (size_t)node * F2 + h0off));

            int k = start;
            for (; k + 3 < end; k += 4) {
                int s0 = g_esrc[k + 0], s1 = g_esrc[k + 1];
                int s2 = g_esrc[k + 2], s3 = g_esrc[k + 3];
                uint2 r0v = *reinterpret_cast<const uint2*>(tin + (size_t)s0 * F2 + h0off);
                uint2 r1v = *reinterpret_cast<const uint2*>(tin + (size_t)s1 * F2 + h0off);
                uint2 r2v = *reinterpret_cast<const uint2*>(tin + (size_t)s2 * F2 + h0off);
                uint2 r3v = *reinterpret_cast<const uint2*>(tin + (size_t)s3 * F2 + h0off);
                acc_half4(a0, r0v);
                acc_half4(a1, r1v);
                acc_half4(a2, r2v);
                acc_half4(a3, r3v);
            }
            for (; k < end; k++) {
                int s0 = g_esrc[k];
                acc_half4(a0, *reinterpret_cast<const uint2*>(tin + (size_t)s0 * F2 + h0off));
            }

            float d = g_dis[node];
            hs[r][c0 + 0] = fmaxf(fmaf(d, (a0.x + a1.x) + (a2.x + a3.x), bv.x), 0.0f);
            hs[r][c0 + 1] = fmaxf(fmaf(d, (a0.y + a1.y) + (a2.y + a3.y), bv.y), 0.0f);
            hs[r][c0 + 2] = fmaxf(fmaf(d, (a0.z + a1.z) + (a2.z + a3.z), bv.z), 0.0f);
            hs[r][c0 + 3] = fmaxf(fmaf(d, (a0.w + a1.w) + (a2.w + a3.w), bv.w), 0.0f);
        } else if (r < F) {
            hs[r][c0 + 0] = 0.0f; hs[r][c0 + 1] = 0.0f;
            hs[r][c0 + 2] = 0.0f; hs[r][c0 + 3] = 0.0f;
        }
    }
    __syncthreads();

    // --- gemm phase ---
    int r0 = grp * 4;
    float acc[4][4];
#pragma unroll
    for (int i = 0; i < 4; i++)
#pragma unroll
        for (int j = 0; j < 4; j++) acc[i][j] = 0.0f;

#pragma unroll 8
    for (int k = 0; k < F; k++) {
        float4 wv = *reinterpret_cast<const float4*>(&Ws[k * F + c0]);
        float h0 = hs[r0 + 0][k], h1 = hs[r0 + 1][k];
        float h2 = hs[r0 + 2][k], h3 = hs[r0 + 3][k];
        acc[0][0] = fmaf(h0, wv.x, acc[0][0]); acc[0][1] = fmaf(h0, wv.y, acc[0][1]);
        acc[0][2] = fmaf(h0, wv.z, acc[0][2]); acc[0][3] = fmaf(h0, wv.w, acc[0][3]);
        acc[1][0] = fmaf(h1, wv.x, acc[1][0]); acc[1][1] = fmaf(h1, wv.y, acc[1][1]);
        acc[1][2] = fmaf(h1, wv.z, acc[1][2]); acc[1][3] = fmaf(h1, wv.w, acc[1][3]);
        acc[2][0] = fmaf(h2, wv.x, acc[2][0]); acc[2][1] = fmaf(h2, wv.y, acc[2][1]);
        acc[2][2] = fmaf(h2, wv.z, acc[2][2]); acc[2][3] = fmaf(h2, wv.w, acc[2][3]);
        acc[3][0] = fmaf(h3, wv.x, acc[3][0]); acc[3][1] = fmaf(h3, wv.y, acc[3][1]);
        acc[3][2] = fmaf(h3, wv.z, acc[3][2]); acc[3][3] = fmaf(h3, wv.w, acc[3][3]);
    }

#pragma unroll
    for (int i = 0; i < 4; i++) {
        int row = row0 + r0 + i;
        if (row < n) {
            float d = g_dis[row];
            __half2 o0 = __floats2half2_rn(acc[i][0] * d, acc[i][1] * d);
            __half2 o1 = __floats2half2_rn(acc[i][2] * d, acc[i][3] * d);
            uint2 pk;
            pk.x = *reinterpret_cast<unsigned int*>(&o0);
            pk.y = *reinterpret_cast<unsigned int*>(&o1);
            *reinterpret_cast<uint2*>(tout + (size_t)row * F2 + h0off) = pk;
        }
    }
}

// ---------------------------------------------------------------------------
// Fused final: agg phase (bias b3) then out = h @ Wl + bl  [64x8]
// ---------------------------------------------------------------------------
__global__ void __launch_bounds__(256) k_fused_final(
        const __half2* __restrict__ tin,
        const float* __restrict__ b,    // b3
        const float* __restrict__ Wl,   // [64,8]
        const float* __restrict__ bl,   // [8]
        float* __restrict__ out,
        int n) {
    __shared__ float Wls[F * OUTF];
    __shared__ float hs[F][F + 1];

    int tid = threadIdx.x;
    int tx  = tid & 15;
    int grp = tid >> 4;
    int row0 = blockIdx.x * F;
    int c0 = tx * 4;
    int h0off = tx * 2;

    for (int i = tid; i < F * OUTF; i += 256) Wls[i] = Wl[i];

    float4 bv = *reinterpret_cast<const float4*>(b + c0);

#pragma unroll
    for (int batch = 0; batch < 4; batch++) {
        int r = batch * 16 + grp;
        int node = row0 + r;
        if (node < n) {
            int end   = g_rowstart[node];
            int start = (node > 0) ? g_rowstart[node - 1] : 0;

            float4 a0 = make_float4(0.f, 0.f, 0.f, 0.f);
            float4 a1 = make_float4(0.f, 0.f, 0.f, 0.f);
            float4 a2 = make_float4(0.f, 0.f, 0.f, 0.f);
            float4 a3 = make_float4(0.f, 0.f, 0.f, 0.f);

            acc_half4(a0, *reinterpret_cast<const uint2*>(tin + (size_t)node * F2 + h0off));

            int k = start;
            for (; k + 3 < end; k += 4) {
                int s0 = g_esrc[k + 0], s1 = g_esrc[k + 1];
                int s2 = g_esrc[k + 2], s3 = g_esrc[k + 3];
                uint2 r0v = *reinterpret_cast<const uint2*>(tin + (size_t)s0 * F2 + h0off);
                uint2 r1v = *reinterpret_cast<const uint2*>(tin + (size_t)s1 * F2 + h0off);
                uint2 r2v = *reinterpret_cast<const uint2*>(tin + (size_t)s2 * F2 + h0off);
                uint2 r3v = *reinterpret_cast<const uint2*>(tin + (size_t)s3 * F2 + h0off);
                acc_half4(a0, r0v);
                acc_half4(a1, r1v);
                acc_half4(a2, r2v);
                acc_half4(a3, r3v);
            }
            for (; k < end; k++) {
                int s0 = g_esrc[k];
                acc_half4(a0, *reinterpret_cast<const uint2*>(tin + (size_t)s0 * F2 + h0off));
            }

            float d = g_dis[node];
            hs[r][c0 + 0] = fmaxf(fmaf(d, (a0.x + a1.x) + (a2.x + a3.x), bv.x), 0.0f);
            hs[r][c0 + 1] = fmaxf(fmaf(d, (a0.y + a1.y) + (a2.y + a3.y), bv.y), 0.0f);
            hs[r][c0 + 2] = fmaxf(fmaf(d, (a0.z + a1.z) + (a2.z + a3.z), bv.z), 0.0f);
            hs[r][c0 + 3] = fmaxf(fmaf(d, (a0.w + a1.w) + (a2.w + a3.w), bv.w), 0.0f);
        } else if (r < F) {
            hs[r][c0 + 0] = 0.0f; hs[r][c0 + 1] = 0.0f;
            hs[r][c0 + 2] = 0.0f; hs[r][c0 + 3] = 0.0f;
        }
    }
    __syncthreads();

    // --- final 64x8 gemm: each thread computes 2 outputs ---
    int r = tid >> 2;                  // 0..63
    int c = (tid & 3) * 2;             // 0,2,4,6
    int row = row0 + r;
    if (row < n) {
        float acc0 = bl[c], acc1 = bl[c + 1];
#pragma unroll
        for (int k = 0; k < F; k++) {
            float h = hs[r][k];
            acc0 = fmaf(h, Wls[k * OUTF + c], acc0);
            acc1 = fmaf(h, Wls[k * OUTF + c + 1], acc1);
        }
        float2 o = make_float2(acc0, acc1);
        *reinterpret_cast<float2*>(out + (size_t)row * OUTF + c) = o;
    }
}

// ---------------------------------------------------------------------------
// Launch
// ---------------------------------------------------------------------------
extern "C" void kernel_launch(void* const* d_in, const int* in_sizes, int n_in,
                              void* d_out, int out_size) {
    const float* x  = (const float*)d_in[0];
    const int*   ei = (const int*)d_in[1];     // int32 edge_index [2, E]
    const float* W1 = (const float*)d_in[2];
    const float* b1 = (const float*)d_in[3];
    const float* W2 = (const float*)d_in[4];
    const float* b2 = (const float*)d_in[5];
    const float* W3 = (const float*)d_in[6];
    const float* b3 = (const float*)d_in[7];
    const float* Wl = (const float*)d_in[8];
    const float* bl = (const float*)d_in[9];
    float* out = (float*)d_out;

    int n = in_sizes[0] / F;        // 100000
    int E = in_sizes[1] / 2;        // 1600000

    unsigned sgrid = (unsigned)((n + SCAN_B - 1) / SCAN_B);

    void* cnt_ptr = nullptr;
    cudaGetSymbolAddress(&cnt_ptr, g_cnt);
    __half2 *tA = nullptr, *tB = nullptr;
    cudaGetSymbolAddress((void**)&tA, g_tmpA);
    cudaGetSymbolAddress((void**)&tB, g_tmpB);

    // --- CSR build (reused by all 3 aggregations) ---
    cudaMemsetAsync(cnt_ptr, 0, (size_t)n * sizeof(int));
    k_count<<<(unsigned)((E / 4 + 255) / 256), 256>>>(ei, E);
    k_scan1<<<sgrid, SCAN_B>>>(n);
    k_scan2<<<1, 512>>>((int)sgrid);
    k_scan3<<<sgrid, SCAN_B>>>(n);
    k_place<<<(unsigned)((E / 2 + 255) / 256), 256>>>(ei, E);

    unsigned tile_grid = (unsigned)((n + F - 1) / F);

    // layer 1 gemm -> A; fused(agg1+gemm2) A->B; fused(agg2+gemm3) B->A;
    // fused final(agg3 + linear) A->out
    k_gemm1<<<tile_grid, 256>>>(x, W1, n);
    k_fused<<<tile_grid, 256>>>(tA, tB, b1, W2, n);
    k_fused<<<tile_grid, 256>>>(tB, tA, b2, W3, n);
    k_fused_final<<<tile_grid, 256>>>(tA, b3, Wl, bl, out, n);
}

// round 10
// speedup vs baseline: 1.3833x; 1.3833x over previous
#include <cuda_runtime.h>
#include <cuda_fp16.h>
#include <mma.h>
#include <cstdint>

using namespace nvcuda;

// Problem constants (GCNN3L: N=100000 nodes, F=64 features, 8 outputs)
#define NN 100000
#define EE 1600000
#define F  64
#define F2 32          // F in half2 units
#define OUTF 8
#define LDH 72         // smem stride in halves (144B rows: 16B aligned, staggered banks)

#define SCAN_B 256

// Scratch (static device globals -- no allocation allowed)
__device__ __align__(256) __half2 g_tmpA[(size_t)NN * F2];  // scaled messages, fp16, buf A
__device__ __align__(256) __half2 g_tmpB[(size_t)NN * F2];  // scaled messages, fp16, buf B
__device__ __align__(256) float g_dis[NN];                  // rsqrt(deg)
__device__ __align__(256) int   g_cnt[NN];                  // in-degree (excl. self loop)
__device__ __align__(256) int   g_rowstart[NN];             // scan -> start; after place -> end
__device__ __align__(256) int   g_bsum[512];
__device__ __align__(256) int   g_esrc[EE];                 // per-edge src, dst-sorted

// ---------------------------------------------------------------------------
// CSR build
// ---------------------------------------------------------------------------
__global__ void k_count(const int* __restrict__ ei, int E) {
    int e4 = blockIdx.x * blockDim.x + threadIdx.x;
    if (e4 * 4 + 3 < E) {
        int4 d = *reinterpret_cast<const int4*>(ei + E + e4 * 4);
        atomicAdd(&g_cnt[d.x], 1);
        atomicAdd(&g_cnt[d.y], 1);
        atomicAdd(&g_cnt[d.z], 1);
        atomicAdd(&g_cnt[d.w], 1);
    } else {
        for (int e = e4 * 4; e < E; e++) atomicAdd(&g_cnt[ei[E + e]], 1);
    }
}

__global__ void k_scan1(int n) {   // block-local exclusive scan + dis
    __shared__ int s[SCAN_B];
    int i = blockIdx.x * SCAN_B + threadIdx.x;
    int v = (i < n) ? g_cnt[i] : 0;
    s[threadIdx.x] = v;
    __syncthreads();
    for (int off = 1; off < SCAN_B; off <<= 1) {
        int t = (threadIdx.x >= off) ? s[threadIdx.x - off] : 0;
        __syncthreads();
        s[threadIdx.x] += t;
        __syncthreads();
    }
    if (i < n) {
        g_rowstart[i] = s[threadIdx.x] - v;   // exclusive within block
        g_dis[i] = rsqrtf((float)(v + 1));    // +1 self loop
    }
    if (threadIdx.x == SCAN_B - 1) g_bsum[blockIdx.x] = s[SCAN_B - 1];
}

// Merged scan2+scan3: every block redundantly scans the (<=512) block sums in
// smem, then adds the right offset to its 512-node slice.
__global__ void k_scan23(int n, int nb) {
    __shared__ int s[512];
    int v = ((int)threadIdx.x < nb) ? g_bsum[threadIdx.x] : 0;
    s[threadIdx.x] = v;
    __syncthreads();
    for (int off = 1; off < 512; off <<= 1) {
        int t = (threadIdx.x >= off) ? s[threadIdx.x - off] : 0;
        __syncthreads();
        s[threadIdx.x] += t;      // inclusive scan of block sums
        __syncthreads();
    }
    int i = blockIdx.x * 512 + threadIdx.x;
    if (i < n) {
        int sb = i >> 8;          // which scan1 block this node belongs to
        int off = (sb > 0) ? s[sb - 1] : 0;
        g_rowstart[i] += off;
    }
}

// Place edges; atomicAdd on rowstart acts as cursor. After this kernel,
// rowstart[i] == row END (inclusive scan), so start(i) = rowstart[i-1].
__global__ void k_place(const int* __restrict__ ei, int E) {
    int e2 = blockIdx.x * blockDim.x + threadIdx.x;
    if (e2 * 2 + 1 < E) {
        int2 s = *reinterpret_cast<const int2*>(ei + e2 * 2);
        int2 d = *reinterpret_cast<const int2*>(ei + E + e2 * 2);
        g_esrc[atomicAdd(&g_rowstart[d.x], 1)] = s.x;
        g_esrc[atomicAdd(&g_rowstart[d.y], 1)] = s.y;
    } else {
        for (int e = e2 * 2; e < E; e++) {
            g_esrc[atomicAdd(&g_rowstart[ei[E + e]], 1)] = ei[e];
        }
    }
}

// ---------------------------------------------------------------------------
// Shared tensor-core GEMM helper: os[64][LDH] (f32) = hs_h[64xLDH] @ Ws_h[64xLDH]
// 8 warps, each computes two 16x16 output tiles. Call with all 256 threads.
// ---------------------------------------------------------------------------
__device__ __forceinline__ void mma_64x64(const __half* hs_h, const __half* Ws_h,
                                          float* os, int tid) {
    int w = tid >> 5;                 // warp 0..7
    int tr  = w >> 1;                 // tile row 0..3
    int tc0 = (w & 1) * 2;            // tile cols tc0, tc0+1

    wmma::fragment<wmma::accumulator, 16, 16, 16, float> c0f, c1f;
    wmma::fill_fragment(c0f, 0.0f);
    wmma::fill_fragment(c1f, 0.0f);

#pragma unroll
    for (int kk = 0; kk < 4; kk++) {
        wmma::fragment<wmma::matrix_a, 16, 16, 16, __half, wmma::row_major> fa;
        wmma::fragment<wmma::matrix_b, 16, 16, 16, __half, wmma::row_major> fb0, fb1;
        wmma::load_matrix_sync(fa,  hs_h + (tr * 16) * LDH + kk * 16, LDH);
        wmma::load_matrix_sync(fb0, Ws_h + (kk * 16) * LDH + tc0 * 16, LDH);
        wmma::load_matrix_sync(fb1, Ws_h + (kk * 16) * LDH + (tc0 + 1) * 16, LDH);
        wmma::mma_sync(c0f, fa, fb0, c0f);
        wmma::mma_sync(c1f, fa, fb1, c1f);
    }
    wmma::store_matrix_sync(os + (tr * 16) * LDH + tc0 * 16, c0f, LDH, wmma::mem_row_major);
    wmma::store_matrix_sync(os + (tr * 16) * LDH + (tc0 + 1) * 16, c1f, LDH, wmma::mem_row_major);
}

// ---------------------------------------------------------------------------
// Layer-1 GEMM (tensor core): tmpA = fp16((x @ W1) * dis)
// ---------------------------------------------------------------------------
__global__ void __launch_bounds__(256) k_gemm1(
        const float* __restrict__ x,
        const float* __restrict__ W,
        int n) {
    __shared__ __half Ws_h[F * LDH];
    __shared__ __half hs_h[F * LDH];
    __shared__ float  os[F * LDH];

    int tid = threadIdx.x;
    int row0 = blockIdx.x * F;

    for (int i = tid; i < F * F; i += 256) {
        Ws_h[(i >> 6) * LDH + (i & 63)] = __float2half(W[i]);
        int r = i >> 6, f = i & 63;
        int row = row0 + r;
        hs_h[r * LDH + f] = __float2half((row < n) ? x[(size_t)row * F + f] : 0.0f);
    }
    __syncthreads();

    mma_64x64(hs_h, Ws_h, os, tid);
    __syncthreads();

    int tx = tid & 15, ty = tid >> 4;
    int c0 = tx * 4;
#pragma unroll
    for (int i = 0; i < 4; i++) {
        int r = ty * 4 + i;
        int row = row0 + r;
        if (row < n) {
            float4 t = *reinterpret_cast<const float4*>(&os[r * LDH + c0]);
            float d = g_dis[row];
            __half2 h0 = __floats2half2_rn(t.x * d, t.y * d);
            __half2 h1 = __floats2half2_rn(t.z * d, t.w * d);
            uint2 pk;
            pk.x = *reinterpret_cast<unsigned int*>(&h0);
            pk.y = *reinterpret_cast<unsigned int*>(&h1);
            *reinterpret_cast<uint2*>(g_tmpA + (size_t)row * F2 + tx * 2) = pk;
        }
    }
}

// ---------------------------------------------------------------------------
// Fused layer: agg (fp16 gather, fp32 accumulate) -> fp16 h -> tensor-core GEMM
// ---------------------------------------------------------------------------
__device__ __forceinline__ void acc_half4(float4& a, uint2 raw) {
    __half2 h0 = *reinterpret_cast<__half2*>(&raw.x);
    __half2 h1 = *reinterpret_cast<__half2*>(&raw.y);
    float2 f0 = __half22float2(h0);
    float2 f1 = __half22float2(h1);
    a.x += f0.x; a.y += f0.y; a.z += f1.x; a.w += f1.y;
}

__global__ void __launch_bounds__(256) k_fused(
        const __half2* __restrict__ tin,
        __half2* __restrict__ tout,
        const float* __restrict__ b,   // bias of the AGG layer
        const float* __restrict__ W,   // weights of the NEXT gemm
        int n) {
    __shared__ __half Ws_h[F * LDH];
    __shared__ __half hs_h[F * LDH];
    __shared__ float  os[F * LDH];

    int tid = threadIdx.x;
    int tx  = tid & 15;                 // col group
    int grp = tid >> 4;                 // node group 0..15
    int row0 = blockIdx.x * F;
    int c0 = tx * 4;                    // float column base
    int h0off = tx * 2;                 // half2 column base

    for (int i = tid; i < F * F; i += 256)
        Ws_h[(i >> 6) * LDH + (i & 63)] = __float2half(W[i]);

    float4 bv = *reinterpret_cast<const float4*>(b + c0);

#pragma unroll
    for (int batch = 0; batch < 4; batch++) {
        int r = batch * 16 + grp;
        int node = row0 + r;
        if (node < n) {
            int end   = g_rowstart[node];
            int start = (node > 0) ? g_rowstart[node - 1] : 0;

            float4 a0 = make_float4(0.f, 0.f, 0.f, 0.f);
            float4 a1 = make_float4(0.f, 0.f, 0.f, 0.f);
            float4 a2 = make_float4(0.f, 0.f, 0.f, 0.f);
            float4 a3 = make_float4(0.f, 0.f, 0.f, 0.f);

            acc_half4(a0, *reinterpret_cast<const uint2*>(tin + (size_t)node * F2 + h0off));

            int k = start;
            for (; k + 3 < end; k += 4) {
                int s0 = g_esrc[k + 0], s1 = g_esrc[k + 1];
                int s2 = g_esrc[k + 2], s3 = g_esrc[k + 3];
                uint2 r0v = *reinterpret_cast<const uint2*>(tin + (size_t)s0 * F2 + h0off);
                uint2 r1v = *reinterpret_cast<const uint2*>(tin + (size_t)s1 * F2 + h0off);
                uint2 r2v = *reinterpret_cast<const uint2*>(tin + (size_t)s2 * F2 + h0off);
                uint2 r3v = *reinterpret_cast<const uint2*>(tin + (size_t)s3 * F2 + h0off);
                acc_half4(a0, r0v);
                acc_half4(a1, r1v);
                acc_half4(a2, r2v);
                acc_half4(a3, r3v);
            }
            for (; k < end; k++) {
                int s0 = g_esrc[k];
                acc_half4(a0, *reinterpret_cast<const uint2*>(tin + (size_t)s0 * F2 + h0off));
            }

            float d = g_dis[node];
            float v0 = fmaxf(fmaf(d, (a0.x + a1.x) + (a2.x + a3.x), bv.x), 0.0f);
            float v1 = fmaxf(fmaf(d, (a0.y + a1.y) + (a2.y + a3.y), bv.y), 0.0f);
            float v2 = fmaxf(fmaf(d, (a0.z + a1.z) + (a2.z + a3.z), bv.z), 0.0f);
            float v3 = fmaxf(fmaf(d, (a0.w + a1.w) + (a2.w + a3.w), bv.w), 0.0f);
            __half2 p0 = __floats2half2_rn(v0, v1);
            __half2 p1 = __floats2half2_rn(v2, v3);
            uint2 pk;
            pk.x = *reinterpret_cast<unsigned int*>(&p0);
            pk.y = *reinterpret_cast<unsigned int*>(&p1);
            *reinterpret_cast<uint2*>(&hs_h[r * LDH + c0]) = pk;
        } else if (r < F) {
            uint2 z = make_uint2(0u, 0u);
            *reinterpret_cast<uint2*>(&hs_h[r * LDH + c0]) = z;
        }
    }
    __syncthreads();

    mma_64x64(hs_h, Ws_h, os, tid);
    __syncthreads();

    int ty = tid >> 4;
#pragma unroll
    for (int i = 0; i < 4; i++) {
        int r = ty * 4 + i;
        int row = row0 + r;
        if (row < n) {
            float4 t = *reinterpret_cast<const float4*>(&os[r * LDH + c0]);
            float d = g_dis[row];
            __half2 o0 = __floats2half2_rn(t.x * d, t.y * d);
            __half2 o1 = __floats2half2_rn(t.z * d, t.w * d);
            uint2 pk;
            pk.x = *reinterpret_cast<unsigned int*>(&o0);
            pk.y = *reinterpret_cast<unsigned int*>(&o1);
            *reinterpret_cast<uint2*>(tout + (size_t)row * F2 + h0off) = pk;
        }
    }
}

// ---------------------------------------------------------------------------
// Fused final: agg phase (bias b3) then out = h @ Wl + bl  [64x8] (fp32 scalar)
// ---------------------------------------------------------------------------
__global__ void __launch_bounds__(256) k_fused_final(
        const __half2* __restrict__ tin,
        const float* __restrict__ b,    // b3
        const float* __restrict__ Wl,   // [64,8]
        const float* __restrict__ bl,   // [8]
        float* __restrict__ out,
        int n) {
    __shared__ float Wls[F * OUTF];
    __shared__ float hs[F][F + 1];

    int tid = threadIdx.x;
    int tx  = tid & 15;
    int grp = tid >> 4;
    int row0 = blockIdx.x * F;
    int c0 = tx * 4;
    int h0off = tx * 2;

    for (int i = tid; i < F * OUTF; i += 256) Wls[i] = Wl[i];

    float4 bv = *reinterpret_cast<const float4*>(b + c0);

#pragma unroll
    for (int batch = 0; batch < 4; batch++) {
        int r = batch * 16 + grp;
        int node = row0 + r;
        if (node < n) {
            int end   = g_rowstart[node];
            int start = (node > 0) ? g_rowstart[node - 1] : 0;

            float4 a0 = make_float4(0.f, 0.f, 0.f, 0.f);
            float4 a1 = make_float4(0.f, 0.f, 0.f, 0.f);
            float4 a2 = make_float4(0.f, 0.f, 0.f, 0.f);
            float4 a3 = make_float4(0.f, 0.f, 0.f, 0.f);

            acc_half4(a0, *reinterpret_cast<const uint2*>(tin + (size_t)node * F2 + h0off));

            int k = start;
            for (; k + 3 < end; k += 4) {
                int s0 = g_esrc[k + 0], s1 = g_esrc[k + 1];
                int s2 = g_esrc[k + 2], s3 = g_esrc[k + 3];
                uint2 r0v = *reinterpret_cast<const uint2*>(tin + (size_t)s0 * F2 + h0off);
                uint2 r1v = *reinterpret_cast<const uint2*>(tin + (size_t)s1 * F2 + h0off);
                uint2 r2v = *reinterpret_cast<const uint2*>(tin + (size_t)s2 * F2 + h0off);
                uint2 r3v = *reinterpret_cast<const uint2*>(tin + (size_t)s3 * F2 + h0off);
                acc_half4(a0, r0v);
                acc_half4(a1, r1v);
                acc_half4(a2, r2v);
                acc_half4(a3, r3v);
            }
            for (; k < end; k++) {
                int s0 = g_esrc[k];
                acc_half4(a0, *reinterpret_cast<const uint2*>(tin + (size_t)s0 * F2 + h0off));
            }

            float d = g_dis[node];
            hs[r][c0 + 0] = fmaxf(fmaf(d, (a0.x + a1.x) + (a2.x + a3.x), bv.x), 0.0f);
            hs[r][c0 + 1] = fmaxf(fmaf(d, (a0.y + a1.y) + (a2.y + a3.y), bv.y), 0.0f);
            hs[r][c0 + 2] = fmaxf(fmaf(d, (a0.z + a1.z) + (a2.z + a3.z), bv.z), 0.0f);
            hs[r][c0 + 3] = fmaxf(fmaf(d, (a0.w + a1.w) + (a2.w + a3.w), bv.w), 0.0f);
        } else if (r < F) {
            hs[r][c0 + 0] = 0.0f; hs[r][c0 + 1] = 0.0f;
            hs[r][c0 + 2] = 0.0f; hs[r][c0 + 3] = 0.0f;
        }
    }
    __syncthreads();

    int r = tid >> 2;                  // 0..63
    int c = (tid & 3) * 2;             // 0,2,4,6
    int row = row0 + r;
    if (row < n) {
        float acc0 = bl[c], acc1 = bl[c + 1];
#pragma unroll
        for (int k = 0; k < F; k++) {
            float h = hs[r][k];
            acc0 = fmaf(h, Wls[k * OUTF + c], acc0);
            acc1 = fmaf(h, Wls[k * OUTF + c + 1], acc1);
        }
        float2 o = make_float2(acc0, acc1);
        *reinterpret_cast<float2*>(out + (size_t)row * OUTF + c) = o;
    }
}

// ---------------------------------------------------------------------------
// Launch
// ---------------------------------------------------------------------------
extern "C" void kernel_launch(void* const* d_in, const int* in_sizes, int n_in,
                              void* d_out, int out_size) {
    const float* x  = (const float*)d_in[0];
    const int*   ei = (const int*)d_in[1];     // int32 edge_index [2, E]
    const float* W1 = (const float*)d_in[2];
    const float* b1 = (const float*)d_in[3];
    const float* W2 = (const float*)d_in[4];
    const float* b2 = (const float*)d_in[5];
    const float* W3 = (const float*)d_in[6];
    const float* b3 = (const float*)d_in[7];
    const float* Wl = (const float*)d_in[8];
    const float* bl = (const float*)d_in[9];
    float* out = (float*)d_out;

    int n = in_sizes[0] / F;        // 100000
    int E = in_sizes[1] / 2;        // 1600000

    unsigned sgrid = (unsigned)((n + SCAN_B - 1) / SCAN_B);   // 391

    void* cnt_ptr = nullptr;
    cudaGetSymbolAddress(&cnt_ptr, g_cnt);
    __half2 *tA = nullptr, *tB = nullptr;
    cudaGetSymbolAddress((void**)&tA, g_tmpA);
    cudaGetSymbolAddress((void**)&tB, g_tmpB);

    // --- CSR build (reused by all 3 aggregations) ---
    cudaMemsetAsync(cnt_ptr, 0, (size_t)n * sizeof(int));
    k_count<<<(unsigned)((E / 4 + 255) / 256), 256>>>(ei, E);
    k_scan1<<<sgrid, SCAN_B>>>(n);
    k_scan23<<<(unsigned)((n + 511) / 512), 512>>>(n, (int)sgrid);
    k_place<<<(unsigned)((E / 2 + 255) / 256), 256>>>(ei, E);

    unsigned tile_grid = (unsigned)((n + F - 1) / F);

    // layer 1 gemm -> A; fused(agg1+gemm2) A->B; fused(agg2+gemm3) B->A;
    // fused final(agg3 + linear) A->out
    k_gemm1<<<tile_grid, 256>>>(x, W1, n);
    k_fused<<<tile_grid, 256>>>(tA, tB, b1, W2, n);
    k_fused<<<tile_grid, 256>>>(tB, tA, b2, W3, n);
    k_fused_final<<<tile_grid, 256>>>(tA, b3, Wl, bl, out, n);
}

// round 11
// speedup vs baseline: 1.4679x; 1.0611x over previous
#include <cuda_runtime.h>
#include <cuda_fp16.h>
#include <mma.h>
#include <cstdint>

using namespace nvcuda;

// Problem constants (GCNN3L: N=100000 nodes, F=64 features, 8 outputs)
#define NN 100000
#define EE 1600000
#define F  64
#define F2 32          // F in half2 units
#define OUTF 8
#define LDH 72         // smem stride in halves (144B rows: 16B aligned, staggered banks)

#define SCAN_B 256

// Scratch (static device globals -- no allocation allowed)
__device__ __align__(256) __half2 g_tmpA[(size_t)NN * F2];  // scaled messages, fp16, buf A
__device__ __align__(256) __half2 g_tmpB[(size_t)NN * F2];  // scaled messages, fp16, buf B
__device__ __align__(256) float g_dis[NN];                  // rsqrt(deg)
__device__ __align__(256) int   g_cnt[NN];                  // in-degree (excl. self loop)
__device__ __align__(256) int   g_rowstart[NN];             // scan -> start; after place -> end
__device__ __align__(256) int   g_bsum[512];
__device__ __align__(256) int   g_esrc[EE];                 // per-edge src, dst-sorted

// ---------------------------------------------------------------------------
// CSR build
// ---------------------------------------------------------------------------
__global__ void k_count(const int* __restrict__ ei, int E) {
    int e4 = blockIdx.x * blockDim.x + threadIdx.x;
    if (e4 * 4 + 3 < E) {
        int4 d = *reinterpret_cast<const int4*>(ei + E + e4 * 4);
        atomicAdd(&g_cnt[d.x], 1);
        atomicAdd(&g_cnt[d.y], 1);
        atomicAdd(&g_cnt[d.z], 1);
        atomicAdd(&g_cnt[d.w], 1);
    } else {
        for (int e = e4 * 4; e < E; e++) atomicAdd(&g_cnt[ei[E + e]], 1);
    }
}

__global__ void k_scan1(int n) {   // block-local exclusive scan + dis
    __shared__ int s[SCAN_B];
    int i = blockIdx.x * SCAN_B + threadIdx.x;
    int v = (i < n) ? g_cnt[i] : 0;
    s[threadIdx.x] = v;
    __syncthreads();
    for (int off = 1; off < SCAN_B; off <<= 1) {
        int t = (threadIdx.x >= off) ? s[threadIdx.x - off] : 0;
        __syncthreads();
        s[threadIdx.x] += t;
        __syncthreads();
    }
    if (i < n) {
        g_rowstart[i] = s[threadIdx.x] - v;   // exclusive within block
        g_dis[i] = rsqrtf((float)(v + 1));    // +1 self loop
    }
    if (threadIdx.x == SCAN_B - 1) g_bsum[blockIdx.x] = s[SCAN_B - 1];
}

// Merged scan2+scan3: every block redundantly scans the (<=512) block sums in
// smem, then adds the right offset to its 512-node slice.
__global__ void k_scan23(int n, int nb) {
    __shared__ int s[512];
    int v = ((int)threadIdx.x < nb) ? g_bsum[threadIdx.x] : 0;
    s[threadIdx.x] = v;
    __syncthreads();
    for (int off = 1; off < 512; off <<= 1) {
        int t = (threadIdx.x >= off) ? s[threadIdx.x - off] : 0;
        __syncthreads();
        s[threadIdx.x] += t;      // inclusive scan of block sums
        __syncthreads();
    }
    int i = blockIdx.x * 512 + threadIdx.x;
    if (i < n) {
        int sb = i >> 8;          // which scan1 block this node belongs to
        int off = (sb > 0) ? s[sb - 1] : 0;
        g_rowstart[i] += off;
    }
}

// Place edges; atomicAdd on rowstart acts as cursor. After this kernel,
// rowstart[i] == row END (inclusive scan), so start(i) = rowstart[i-1].
// 4 edges/thread for MLP on the ATOMG path.
__global__ void k_place(const int* __restrict__ ei, int E) {
    int base = (blockIdx.x * blockDim.x + threadIdx.x) * 4;
    if (base + 3 < E) {
        int4 s = *reinterpret_cast<const int4*>(ei + base);
        int4 d = *reinterpret_cast<const int4*>(ei + E + base);
        int p0 = atomicAdd(&g_rowstart[d.x], 1);
        int p1 = atomicAdd(&g_rowstart[d.y], 1);
        int p2 = atomicAdd(&g_rowstart[d.z], 1);
        int p3 = atomicAdd(&g_rowstart[d.w], 1);
        g_esrc[p0] = s.x;
        g_esrc[p1] = s.y;
        g_esrc[p2] = s.z;
        g_esrc[p3] = s.w;
    } else {
        for (int e = base; e < E; e++) {
            g_esrc[atomicAdd(&g_rowstart[ei[E + e]], 1)] = ei[e];
        }
    }
}

// ---------------------------------------------------------------------------
// Tensor-core GEMM with smem overlay: os (f32, 64xLDH) ALIASES Ws_h/hs_h.
// Fragments accumulate in registers; block-wide sync; then store into overlay.
// ---------------------------------------------------------------------------
__device__ __forceinline__ void mma_64x64_overlay(const __half* hs_h, const __half* Ws_h,
                                                  float* os, int tid) {
    int w = tid >> 5;                 // warp 0..7
    int tr  = w >> 1;                 // tile row 0..3
    int tc0 = (w & 1) * 2;            // tile cols tc0, tc0+1

    wmma::fragment<wmma::accumulator, 16, 16, 16, float> c0f, c1f;
    wmma::fill_fragment(c0f, 0.0f);
    wmma::fill_fragment(c1f, 0.0f);

#pragma unroll
    for (int kk = 0; kk < 4; kk++) {
        wmma::fragment<wmma::matrix_a, 16, 16, 16, __half, wmma::row_major> fa;
        wmma::fragment<wmma::matrix_b, 16, 16, 16, __half, wmma::row_major> fb0, fb1;
        wmma::load_matrix_sync(fa,  hs_h + (tr * 16) * LDH + kk * 16, LDH);
        wmma::load_matrix_sync(fb0, Ws_h + (kk * 16) * LDH + tc0 * 16, LDH);
        wmma::load_matrix_sync(fb1, Ws_h + (kk * 16) * LDH + (tc0 + 1) * 16, LDH);
        wmma::mma_sync(c0f, fa, fb0, c0f);
        wmma::mma_sync(c1f, fa, fb1, c1f);
    }
    __syncthreads();   // all warps done READING hs_h/Ws_h; safe to overwrite
    wmma::store_matrix_sync(os + (tr * 16) * LDH + tc0 * 16, c0f, LDH, wmma::mem_row_major);
    wmma::store_matrix_sync(os + (tr * 16) * LDH + (tc0 + 1) * 16, c1f, LDH, wmma::mem_row_major);
}

// ---------------------------------------------------------------------------
// Layer-1 GEMM (tensor core): tmpA = fp16((x @ W1) * dis)
// ---------------------------------------------------------------------------
__global__ void __launch_bounds__(256) k_gemm1(
        const float* __restrict__ x,
        const float* __restrict__ W,
        int n) {
    __shared__ __align__(16) char smem_raw[F * LDH * 4];   // 18432 B
    __half* Ws_h = reinterpret_cast<__half*>(smem_raw);            // [F*LDH]
    __half* hs_h = Ws_h + F * LDH;                                 // [F*LDH]
    float*  os   = reinterpret_cast<float*>(smem_raw);             // overlays both

    int tid = threadIdx.x;
    int row0 = blockIdx.x * F;

    for (int i = tid; i < F * F; i += 256) {
        int r = i >> 6, f = i & 63;
        Ws_h[r * LDH + f] = __float2half(W[i]);
        int row = row0 + r;
        hs_h[r * LDH + f] = __float2half((row < n) ? x[(size_t)row * F + f] : 0.0f);
    }
    __syncthreads();

    mma_64x64_overlay(hs_h, Ws_h, os, tid);
    __syncthreads();

    int tx = tid & 15, ty = tid >> 4;
    int c0 = tx * 4;
#pragma unroll
    for (int i = 0; i < 4; i++) {
        int r = ty * 4 + i;
        int row = row0 + r;
        if (row < n) {
            float4 t = *reinterpret_cast<const float4*>(&os[r * LDH + c0]);
            float d = g_dis[row];
            __half2 h0 = __floats2half2_rn(t.x * d, t.y * d);
            __half2 h1 = __floats2half2_rn(t.z * d, t.w * d);
            uint2 pk;
            pk.x = *reinterpret_cast<unsigned int*>(&h0);
            pk.y = *reinterpret_cast<unsigned int*>(&h1);
            *reinterpret_cast<uint2*>(g_tmpA + (size_t)row * F2 + tx * 2) = pk;
        }
    }
}

// ---------------------------------------------------------------------------
// Fused layer: agg (fp16 gather, fp32 accumulate, 8 chains) -> tensor-core GEMM
// ---------------------------------------------------------------------------
__device__ __forceinline__ void acc_half4(float4& a, uint2 raw) {
    __half2 h0 = *reinterpret_cast<__half2*>(&raw.x);
    __half2 h1 = *reinterpret_cast<__half2*>(&raw.y);
    float2 f0 = __half22float2(h0);
    float2 f1 = __half22float2(h1);
    a.x += f0.x; a.y += f0.y; a.z += f1.x; a.w += f1.y;
}

__global__ void __launch_bounds__(256) k_fused(
        const __half2* __restrict__ tin,
        __half2* __restrict__ tout,
        const float* __restrict__ b,   // bias of the AGG layer
        const float* __restrict__ W,   // weights of the NEXT gemm
        int n) {
    __shared__ __align__(16) char smem_raw[F * LDH * 4];   // 18432 B
    __half* Ws_h = reinterpret_cast<__half*>(smem_raw);
    __half* hs_h = Ws_h + F * LDH;
    float*  os   = reinterpret_cast<float*>(smem_raw);

    int tid = threadIdx.x;
    int tx  = tid & 15;                 // col group
    int grp = tid >> 4;                 // node group 0..15
    int row0 = blockIdx.x * F;
    int c0 = tx * 4;                    // float column base
    int h0off = tx * 2;                 // half2 column base

    for (int i = tid; i < F * F; i += 256)
        Ws_h[(i >> 6) * LDH + (i & 63)] = __float2half(W[i]);

    float4 bv = *reinterpret_cast<const float4*>(b + c0);

#pragma unroll
    for (int batch = 0; batch < 4; batch++) {
        int r = batch * 16 + grp;
        int node = row0 + r;
        if (node < n) {
            int end   = g_rowstart[node];
            int start = (node > 0) ? g_rowstart[node - 1] : 0;

            float4 a0 = make_float4(0.f, 0.f, 0.f, 0.f);
            float4 a1 = make_float4(0.f, 0.f, 0.f, 0.f);
            float4 a2 = make_float4(0.f, 0.f, 0.f, 0.f);
            float4 a3 = make_float4(0.f, 0.f, 0.f, 0.f);

            acc_half4(a0, *reinterpret_cast<const uint2*>(tin + (size_t)node * F2 + h0off));

            int k = start;
            for (; k + 7 < end; k += 8) {
                int s0 = g_esrc[k + 0], s1 = g_esrc[k + 1];
                int s2 = g_esrc[k + 2], s3 = g_esrc[k + 3];
                int s4 = g_esrc[k + 4], s5 = g_esrc[k + 5];
                int s6 = g_esrc[k + 6], s7 = g_esrc[k + 7];
                uint2 v0 = *reinterpret_cast<const uint2*>(tin + (size_t)s0 * F2 + h0off);
                uint2 v1 = *reinterpret_cast<const uint2*>(tin + (size_t)s1 * F2 + h0off);
                uint2 v2 = *reinterpret_cast<const uint2*>(tin + (size_t)s2 * F2 + h0off);
                uint2 v3 = *reinterpret_cast<const uint2*>(tin + (size_t)s3 * F2 + h0off);
                uint2 v4 = *reinterpret_cast<const uint2*>(tin + (size_t)s4 * F2 + h0off);
                uint2 v5 = *reinterpret_cast<const uint2*>(tin + (size_t)s5 * F2 + h0off);
                uint2 v6 = *reinterpret_cast<const uint2*>(tin + (size_t)s6 * F2 + h0off);
                uint2 v7 = *reinterpret_cast<const uint2*>(tin + (size_t)s7 * F2 + h0off);
                acc_half4(a0, v0); acc_half4(a1, v1);
                acc_half4(a2, v2); acc_half4(a3, v3);
                acc_half4(a0, v4); acc_half4(a1, v5);
                acc_half4(a2, v6); acc_half4(a3, v7);
            }
            for (; k + 3 < end; k += 4) {
                int s0 = g_esrc[k + 0], s1 = g_esrc[k + 1];
                int s2 = g_esrc[k + 2], s3 = g_esrc[k + 3];
                uint2 v0 = *reinterpret_cast<const uint2*>(tin + (size_t)s0 * F2 + h0off);
                uint2 v1 = *reinterpret_cast<const uint2*>(tin + (size_t)s1 * F2 + h0off);
                uint2 v2 = *reinterpret_cast<const uint2*>(tin + (size_t)s2 * F2 + h0off);
                uint2 v3 = *reinterpret_cast<const uint2*>(tin + (size_t)s3 * F2 + h0off);
                acc_half4(a0, v0); acc_half4(a1, v1);
                acc_half4(a2, v2); acc_half4(a3, v3);
            }
            for (; k < end; k++) {
                int s0 = g_esrc[k];
                acc_half4(a0, *reinterpret_cast<const uint2*>(tin + (size_t)s0 * F2 + h0off));
            }

            float d = g_dis[node];
            float v0 = fmaxf(fmaf(d, (a0.x + a1.x) + (a2.x + a3.x), bv.x), 0.0f);
            float v1 = fmaxf(fmaf(d, (a0.y + a1.y) + (a2.y + a3.y), bv.y), 0.0f);
            float v2 = fmaxf(fmaf(d, (a0.z + a1.z) + (a2.z + a3.z), bv.z), 0.0f);
            float v3 = fmaxf(fmaf(d, (a0.w + a1.w) + (a2.w + a3.w), bv.w), 0.0f);
            __half2 p0 = __floats2half2_rn(v0, v1);
            __half2 p1 = __floats2half2_rn(v2, v3);
            uint2 pk;
            pk.x = *reinterpret_cast<unsigned int*>(&p0);
            pk.y = *reinterpret_cast<unsigned int*>(&p1);
            *reinterpret_cast<uint2*>(&hs_h[r * LDH + c0]) = pk;
        } else if (r < F) {
            uint2 z = make_uint2(0u, 0u);
            *reinterpret_cast<uint2*>(&hs_h[r * LDH + c0]) = z;
        }
    }
    __syncthreads();

    mma_64x64_overlay(hs_h, Ws_h, os, tid);
    __syncthreads();

    int ty = tid >> 4;
#pragma unroll
    for (int i = 0; i < 4; i++) {
        int r = ty * 4 + i;
        int row = row0 + r;
        if (row < n) {
            float4 t = *reinterpret_cast<const float4*>(&os[r * LDH + c0]);
            float d = g_dis[row];
            __half2 o0 = __floats2half2_rn(t.x * d, t.y * d);
            __half2 o1 = __floats2half2_rn(t.z * d, t.w * d);
            uint2 pk;
            pk.x = *reinterpret_cast<unsigned int*>(&o0);
            pk.y = *reinterpret_cast<unsigned int*>(&o1);
            *reinterpret_cast<uint2*>(tout + (size_t)row * F2 + h0off) = pk;
        }
    }
}

// ---------------------------------------------------------------------------
// Fused final: agg phase (bias b3, 8 chains) then out = h @ Wl + bl  [64x8]
// ---------------------------------------------------------------------------
__global__ void __launch_bounds__(256) k_fused_final(
        const __half2* __restrict__ tin,
        const float* __restrict__ b,    // b3
        const float* __restrict__ Wl,   // [64,8]
        const float* __restrict__ bl,   // [8]
        float* __restrict__ out,
        int n) {
    __shared__ float Wls[F * OUTF];
    __shared__ float hs[F][F + 1];

    int tid = threadIdx.x;
    int tx  = tid & 15;
    int grp = tid >> 4;
    int row0 = blockIdx.x * F;
    int c0 = tx * 4;
    int h0off = tx * 2;

    for (int i = tid; i < F * OUTF; i += 256) Wls[i] = Wl[i];

    float4 bv = *reinterpret_cast<const float4*>(b + c0);

#pragma unroll
    for (int batch = 0; batch < 4; batch++) {
        int r = batch * 16 + grp;
        int node = row0 + r;
        if (node < n) {
            int end   = g_rowstart[node];
            int start = (node > 0) ? g_rowstart[node - 1] : 0;

            float4 a0 = make_float4(0.f, 0.f, 0.f, 0.f);
            float4 a1 = make_float4(0.f, 0.f, 0.f, 0.f);
            float4 a2 = make_float4(0.f, 0.f, 0.f, 0.f);
            float4 a3 = make_float4(0.f, 0.f, 0.f, 0.f);

            acc_half4(a0, *reinterpret_cast<const uint2*>(tin + (size_t)node * F2 + h0off));

            int k = start;
            for (; k + 7 < end; k += 8) {
                int s0 = g_esrc[k + 0], s1 = g_esrc[k + 1];
                int s2 = g_esrc[k + 2], s3 = g_esrc[k + 3];
                int s4 = g_esrc[k + 4], s5 = g_esrc[k + 5];
                int s6 = g_esrc[k + 6], s7 = g_esrc[k + 7];
                uint2 v0 = *reinterpret_cast<const uint2*>(tin + (size_t)s0 * F2 + h0off);
                uint2 v1 = *reinterpret_cast<const uint2*>(tin + (size_t)s1 * F2 + h0off);
                uint2 v2 = *reinterpret_cast<const uint2*>(tin + (size_t)s2 * F2 + h0off);
                uint2 v3 = *reinterpret_cast<const uint2*>(tin + (size_t)s3 * F2 + h0off);
                uint2 v4 = *reinterpret_cast<const uint2*>(tin + (size_t)s4 * F2 + h0off);
                uint2 v5 = *reinterpret_cast<const uint2*>(tin + (size_t)s5 * F2 + h0off);
                uint2 v6 = *reinterpret_cast<const uint2*>(tin + (size_t)s6 * F2 + h0off);
                uint2 v7 = *reinterpret_cast<const uint2*>(tin + (size_t)s7 * F2 + h0off);
                acc_half4(a0, v0); acc_half4(a1, v1);
                acc_half4(a2, v2); acc_half4(a3, v3);
                acc_half4(a0, v4); acc_half4(a1, v5);
                acc_half4(a2, v6); acc_half4(a3, v7);
            }
            for (; k + 3 < end; k += 4) {
                int s0 = g_esrc[k + 0], s1 = g_esrc[k + 1];
                int s2 = g_esrc[k + 2], s3 = g_esrc[k + 3];
                uint2 v0 = *reinterpret_cast<const uint2*>(tin + (size_t)s0 * F2 + h0off);
                uint2 v1 = *reinterpret_cast<const uint2*>(tin + (size_t)s1 * F2 + h0off);
                uint2 v2 = *reinterpret_cast<const uint2*>(tin + (size_t)s2 * F2 + h0off);
                uint2 v3 = *reinterpret_cast<const uint2*>(tin + (size_t)s3 * F2 + h0off);
                acc_half4(a0, v0); acc_half4(a1, v1);
                acc_half4(a2, v2); acc_half4(a3, v3);
            }
            for (; k < end; k++) {
                int s0 = g_esrc[k];
                acc_half4(a0, *reinterpret_cast<const uint2*>(tin + (size_t)s0 * F2 + h0off));
            }

            float d = g_dis[node];
            hs[r][c0 + 0] = fmaxf(fmaf(d, (a0.x + a1.x) + (a2.x + a3.x), bv.x), 0.0f);
            hs[r][c0 + 1] = fmaxf(fmaf(d, (a0.y + a1.y) + (a2.y + a3.y), bv.y), 0.0f);
            hs[r][c0 + 2] = fmaxf(fmaf(d, (a0.z + a1.z) + (a2.z + a3.z), bv.z), 0.0f);
            hs[r][c0 + 3] = fmaxf(fmaf(d, (a0.w + a1.w) + (a2.w + a3.w), bv.w), 0.0f);
        } else if (r < F) {
            hs[r][c0 + 0] = 0.0f; hs[r][c0 + 1] = 0.0f;
            hs[r][c0 + 2] = 0.0f; hs[r][c0 + 3] = 0.0f;
        }
    }
    __syncthreads();

    int r = tid >> 2;                  // 0..63
    int c = (tid & 3) * 2;             // 0,2,4,6
    int row = row0 + r;
    if (row < n) {
        float acc0 = bl[c], acc1 = bl[c + 1];
#pragma unroll
        for (int k = 0; k < F; k++) {
            float h = hs[r][k];
            acc0 = fmaf(h, Wls[k * OUTF + c], acc0);
            acc1 = fmaf(h, Wls[k * OUTF + c + 1], acc1);
        }
        float2 o = make_float2(acc0, acc1);
        *reinterpret_cast<float2*>(out + (size_t)row * OUTF + c) = o;
    }
}

// ---------------------------------------------------------------------------
// Launch
// ---------------------------------------------------------------------------
extern "C" void kernel_launch(void* const* d_in, const int* in_sizes, int n_in,
                              void* d_out, int out_size) {
    const float* x  = (const float*)d_in[0];
    const int*   ei = (const int*)d_in[1];     // int32 edge_index [2, E]
    const float* W1 = (const float*)d_in[2];
    const float* b1 = (const float*)d_in[3];
    const float* W2 = (const float*)d_in[4];
    const float* b2 = (const float*)d_in[5];
    const float* W3 = (const float*)d_in[6];
    const float* b3 = (const float*)d_in[7];
    const float* Wl = (const float*)d_in[8];
    const float* bl = (const float*)d_in[9];
    float* out = (float*)d_out;

    int n = in_sizes[0] / F;        // 100000
    int E = in_sizes[1] / 2;        // 1600000

    unsigned sgrid = (unsigned)((n + SCAN_B - 1) / SCAN_B);   // 391

    void* cnt_ptr = nullptr;
    cudaGetSymbolAddress(&cnt_ptr, g_cnt);
    __half2 *tA = nullptr, *tB = nullptr;
    cudaGetSymbolAddress((void**)&tA, g_tmpA);
    cudaGetSymbolAddress((void**)&tB, g_tmpB);

    // --- CSR build (reused by all 3 aggregations) ---
    cudaMemsetAsync(cnt_ptr, 0, (size_t)n * sizeof(int));
    k_count<<<(unsigned)((E / 4 + 255) / 256), 256>>>(ei, E);
    k_scan1<<<sgrid, SCAN_B>>>(n);
    k_scan23<<<(unsigned)((n + 511) / 512), 512>>>(n, (int)sgrid);
    k_place<<<(unsigned)((E / 4 + 255) / 256), 256>>>(ei, E);

    unsigned tile_grid = (unsigned)((n + F - 1) / F);

    // layer 1 gemm -> A; fused(agg1+gemm2) A->B; fused(agg2+gemm3) B->A;
    // fused final(agg3 + linear) A->out
    k_gemm1<<<tile_grid, 256>>>(x, W1, n);
    k_fused<<<tile_grid, 256>>>(tA, tB, b1, W2, n);
    k_fused<<<tile_grid, 256>>>(tB, tA, b2, W3, n);
    k_fused_final<<<tile_grid, 256>>>(tA, b3, Wl, bl, out, n);
}